// round 1
// baseline (speedup 1.0000x reference)
#include <cuda_runtime.h>
#include <cstdint>

#define B_ 32
#define S_ 4096
#define K_ 1024
#define H_ 1024
#define V_ 1024

#define TM 128
#define TN 128
#define SSTR 20   // smem row stride in floats (16 data + 4 pad) -> conflict-free frag loads

// ---------------- scratch (no allocations allowed) ----------------
__device__ float g_qproj[B_ * H_];        // q_proj + Wq_b + Wk_b folded
__device__ float g_scores[B_ * S_];       // masked pre-softmax scores
__device__ float g_ctx_part[8 * B_ * V_]; // split-S partial contexts

// ---------------- helpers ----------------
__device__ __forceinline__ uint32_t f2tf32(float x) {
    uint32_t r;
    asm("cvt.rna.tf32.f32 %0, %1;" : "=r"(r) : "f"(x));
    return r;
}

__device__ __forceinline__ void cpa16(void* s, const void* g) {
    uint32_t sa = (uint32_t)__cvta_generic_to_shared(s);
    asm volatile("cp.async.cg.shared.global [%0], [%1], 16;" :: "r"(sa), "l"(g));
}
__device__ __forceinline__ void cp_commit() { asm volatile("cp.async.commit_group;"); }
template <int N> __device__ __forceinline__ void cp_wait() {
    asm volatile("cp.async.wait_group %0;" :: "n"(N));
}

__device__ __forceinline__ float tanh_fast(float x) {
    // accurate to ~1e-7 abs; avoids tanh.approx accuracy risk and IEEE div
    float ax = fabsf(x);
    float e  = __expf(-2.0f * ax);
    float t  = __fdividef(1.0f - e, 1.0f + e);
    return copysignf(t, x);
}

__device__ __forceinline__ void mma_tf32(float c[4], const uint32_t a[4], const uint32_t b[2]) {
    asm volatile(
        "mma.sync.aligned.m16n8k8.row.col.f32.tf32.tf32.f32 "
        "{%0,%1,%2,%3}, {%4,%5,%6,%7}, {%8,%9}, {%0,%1,%2,%3};"
        : "+f"(c[0]), "+f"(c[1]), "+f"(c[2]), "+f"(c[3])
        : "r"(a[0]), "r"(a[1]), "r"(a[2]), "r"(a[3]), "r"(b[0]), "r"(b[1]));
}

// ---------------- kernel 1: q_proj (fp32 exact) ----------------
__global__ void qproj_kernel(const float* __restrict__ query,
                             const float* __restrict__ Wq_w,
                             const float* __restrict__ Wq_b,
                             const float* __restrict__ Wk_b) {
    __shared__ float q[K_];
    int b = blockIdx.x, hbase = blockIdx.y * 128;
    int tid = threadIdx.x;
    for (int i = tid; i < K_; i += 256) q[i] = query[b * K_ + i];
    __syncthreads();
    int warp = tid >> 5, lane = tid & 31;
    for (int i = 0; i < 16; i++) {
        int h = hbase + warp * 16 + i;
        const float* wr = Wq_w + (size_t)h * K_;
        float acc = 0.f;
        #pragma unroll 8
        for (int k = lane; k < K_; k += 32) acc += q[k] * wr[k];
        #pragma unroll
        for (int o = 16; o; o >>= 1) acc += __shfl_xor_sync(0xffffffffu, acc, o);
        if (lane == 0) g_qproj[b * H_ + h] = acc + Wq_b[h] + Wk_b[h];
    }
}

// ---------------- kernel 2: fused k_proj GEMM + tanh + v_w reduce ----------------
// block: 256 thr (8 warps), tile M=128 rows(b,s) x full H reduction, tf32 mma.sync
__global__ __launch_bounds__(256, 1) void scores_kernel(
    const float* __restrict__ keys, const float* __restrict__ Wk,
    const int* __restrict__ mask, const float* __restrict__ v_w) {
    __shared__ float Ks[2][TM * SSTR];
    __shared__ float Ws[2][TN * SSTR];
    __shared__ float qs[TN];
    __shared__ float vs[TN];
    __shared__ float sscore[TM];

    int bid  = blockIdx.x;
    int b    = bid >> 5;           // 32 row-blocks per batch
    int row0 = (bid & 31) * TM;
    int tid  = threadIdx.x;
    int warp = tid >> 5, lane = tid & 31;
    int wm = warp >> 1, wn = warp & 1;   // 4x2 warp grid: 32x64 warp tiles

    if (tid < TM) sscore[tid] = 0.f;

    const float* kbase = keys + ((size_t)b * S_ + row0) * K_;
    float sacc[4] = {0.f, 0.f, 0.f, 0.f};  // persistent row-partials across h-tiles

    for (int ht = 0; ht < H_ / TN; ht++) {
        int h0 = ht * TN;
        __syncthreads();  // qs/vs overwrite vs previous epilogue; covers sscore init
        if (tid < TN) {
            qs[tid] = g_qproj[b * H_ + h0 + tid];
            vs[tid] = v_w[h0 + tid];
        }
        const float* wbase = Wk + (size_t)h0 * K_;

        float c[2][8][4];
        #pragma unroll
        for (int mt = 0; mt < 2; mt++)
            #pragma unroll
            for (int nt = 0; nt < 8; nt++)
                #pragma unroll
                for (int j = 0; j < 4; j++) c[mt][nt][j] = 0.f;

        // prologue: k-tile 0 -> buf 0
        #pragma unroll
        for (int i = 0; i < 2; i++) {
            int idx = tid + i * 256;
            int r = idx >> 2, c4 = idx & 3;
            cpa16(&Ks[0][r * SSTR + c4 * 4], kbase + (size_t)r * K_ + c4 * 4);
            cpa16(&Ws[0][r * SSTR + c4 * 4], wbase + (size_t)r * K_ + c4 * 4);
        }
        cp_commit();

        for (int kt = 0; kt < K_ / 16; kt++) {
            int cur = kt & 1;
            if (kt + 1 < K_ / 16) {
                int nb = cur ^ 1;
                int koff = (kt + 1) * 16;
                #pragma unroll
                for (int i = 0; i < 2; i++) {
                    int idx = tid + i * 256;
                    int r = idx >> 2, c4 = idx & 3;
                    cpa16(&Ks[nb][r * SSTR + c4 * 4], kbase + (size_t)r * K_ + koff + c4 * 4);
                    cpa16(&Ws[nb][r * SSTR + c4 * 4], wbase + (size_t)r * K_ + koff + c4 * 4);
                }
                cp_commit();
                cp_wait<1>();
            } else {
                cp_wait<0>();
            }
            __syncthreads();

            const float* ks = Ks[cur];
            const float* ws = Ws[cur];
            #pragma unroll
            for (int ksub = 0; ksub < 16; ksub += 8) {
                uint32_t a[2][4];
                int ar = wm * 32 + (lane >> 2);
                int ac = ksub + (lane & 3);
                #pragma unroll
                for (int mt = 0; mt < 2; mt++) {
                    int r = ar + mt * 16;
                    a[mt][0] = f2tf32(ks[r * SSTR + ac]);
                    a[mt][1] = f2tf32(ks[(r + 8) * SSTR + ac]);
                    a[mt][2] = f2tf32(ks[r * SSTR + ac + 4]);
                    a[mt][3] = f2tf32(ks[(r + 8) * SSTR + ac + 4]);
                }
                uint32_t bf[8][2];
                int bc = wn * 64 + (lane >> 2);
                int br = ksub + (lane & 3);
                #pragma unroll
                for (int nt = 0; nt < 8; nt++) {
                    int n = bc + nt * 8;
                    bf[nt][0] = f2tf32(ws[n * SSTR + br]);
                    bf[nt][1] = f2tf32(ws[n * SSTR + br + 4]);
                }
                #pragma unroll
                for (int mt = 0; mt < 2; mt++)
                    #pragma unroll
                    for (int nt = 0; nt < 8; nt++)
                        mma_tf32(c[mt][nt], a[mt], bf[nt]);
            }
            __syncthreads();
        }

        // fused epilogue: scores += tanh(c + q_proj) * v_w
        #pragma unroll
        for (int mt = 0; mt < 2; mt++) {
            #pragma unroll
            for (int nt = 0; nt < 8; nt++) {
                int col = wn * 64 + nt * 8 + (lane & 3) * 2;
                float q0 = qs[col], q1 = qs[col + 1];
                float v0 = vs[col], v1 = vs[col + 1];
                sacc[mt * 2 + 0] += tanh_fast(c[mt][nt][0] + q0) * v0 +
                                    tanh_fast(c[mt][nt][1] + q1) * v1;
                sacc[mt * 2 + 1] += tanh_fast(c[mt][nt][2] + q0) * v0 +
                                    tanh_fast(c[mt][nt][3] + q1) * v1;
            }
        }
    }

    // reduce over the quad (lane&3 spans the 8 columns of each n-tile)
    #pragma unroll
    for (int i = 0; i < 4; i++) {
        sacc[i] += __shfl_xor_sync(0xffffffffu, sacc[i], 1);
        sacc[i] += __shfl_xor_sync(0xffffffffu, sacc[i], 2);
    }
    __syncthreads();
    if ((lane & 3) == 0) {
        int r = wm * 32 + (lane >> 2);
        atomicAdd(&sscore[r],      sacc[0]);
        atomicAdd(&sscore[r + 8],  sacc[1]);
        atomicAdd(&sscore[r + 16], sacc[2]);
        atomicAdd(&sscore[r + 24], sacc[3]);
    }
    __syncthreads();
    if (tid < TM) {
        int srow = row0 + tid;
        float v = sscore[tid];
        g_scores[b * S_ + srow] =
            (mask[b * S_ + srow] == 0) ? __int_as_float(0xff800000) : v;
    }
}

// ---------------- kernel 3: masked softmax -> attention_weights ----------------
__global__ void softmax_kernel(float* __restrict__ w_out) {
    __shared__ float red[8];
    __shared__ float bval;
    int b = blockIdx.x, tid = threadIdx.x;
    int warp = tid >> 5, lane = tid & 31;
    const float* sc = g_scores + b * S_;

    float m = __int_as_float(0xff800000);
    for (int s = tid; s < S_; s += 256) m = fmaxf(m, sc[s]);
    #pragma unroll
    for (int o = 16; o; o >>= 1) m = fmaxf(m, __shfl_xor_sync(0xffffffffu, m, o));
    if (lane == 0) red[warp] = m;
    __syncthreads();
    if (warp == 0) {
        float v = (lane < 8) ? red[lane] : __int_as_float(0xff800000);
        #pragma unroll
        for (int o = 4; o; o >>= 1) v = fmaxf(v, __shfl_xor_sync(0xffffffffu, v, o));
        if (lane == 0) bval = v;
    }
    __syncthreads();
    float mm = bval;

    float sum = 0.f;
    float* wb = w_out + b * S_;
    for (int s = tid; s < S_; s += 256) {
        float e = expf(sc[s] - mm);  // masked (-inf) -> 0
        wb[s] = e;
        sum += e;
    }
    #pragma unroll
    for (int o = 16; o; o >>= 1) sum += __shfl_xor_sync(0xffffffffu, sum, o);
    if (lane == 0) red[warp] = sum;
    __syncthreads();
    if (warp == 0) {
        float v = (lane < 8) ? red[lane] : 0.f;
        #pragma unroll
        for (int o = 4; o; o >>= 1) v += __shfl_xor_sync(0xffffffffu, v, o);
        if (lane == 0) bval = v;
    }
    __syncthreads();
    float inv = 1.0f / bval;
    for (int s = tid; s < S_; s += 256) wb[s] *= inv;
}

// ---------------- kernel 4: context = attn @ values (split-S, HBM bound) --------
__global__ void context_part_kernel(const float* __restrict__ values,
                                    const float* __restrict__ w) {
    int b = blockIdx.x >> 3;
    int p = blockIdx.x & 7;
    int tid = threadIdx.x;  // 256 -> one float4 column each
    int s0 = p * (S_ / 8);
    const float4* vp = (const float4*)(values + ((size_t)b * S_ + s0) * V_) + tid;
    const float* wb = w + b * S_ + s0;
    float4 acc = make_float4(0.f, 0.f, 0.f, 0.f);
    #pragma unroll 4
    for (int s = 0; s < S_ / 8; s++) {
        float ws = __ldg(wb + s);
        float4 v = __ldg(vp + (size_t)s * (V_ / 4));
        acc.x += ws * v.x; acc.y += ws * v.y; acc.z += ws * v.z; acc.w += ws * v.w;
    }
    ((float4*)g_ctx_part)[((size_t)p * B_ + b) * (V_ / 4) + tid] = acc;
}

__global__ void context_reduce_kernel(float* __restrict__ ctx) {
    int b = blockIdx.x, tid = threadIdx.x;
    for (int i = tid; i < V_; i += 256) {
        float s = 0.f;
        #pragma unroll
        for (int p = 0; p < 8; p++) s += g_ctx_part[((size_t)p * B_ + b) * V_ + i];
        ctx[b * V_ + i] = s;
    }
}

// ---------------- launch ----------------
extern "C" void kernel_launch(void* const* d_in, const int* in_sizes, int n_in,
                              void* d_out, int out_size) {
    const float* query  = (const float*)d_in[0];
    const float* keys   = (const float*)d_in[1];
    const float* values = (const float*)d_in[2];
    const int*   mask   = (const int*)d_in[3];
    const float* Wq_w   = (const float*)d_in[4];
    const float* Wq_b   = (const float*)d_in[5];
    const float* Wk_w   = (const float*)d_in[6];
    const float* Wk_b   = (const float*)d_in[7];
    const float* v_w    = (const float*)d_in[8];
    (void)in_sizes; (void)n_in; (void)out_size;

    float* out     = (float*)d_out;
    float* out_ctx = out;                 // context: [32,1024]
    float* out_w   = out + B_ * V_;       // attention_weights: [32,4096]

    qproj_kernel<<<dim3(B_, H_ / 128), 256>>>(query, Wq_w, Wq_b, Wk_b);
    scores_kernel<<<(B_ * S_) / TM, 256>>>(keys, Wk_w, mask, v_w);
    softmax_kernel<<<B_, 256>>>(out_w);
    context_part_kernel<<<B_ * 8, 256>>>(values, out_w);
    context_reduce_kernel<<<B_, 256>>>(out_ctx);
}

// round 3
// speedup vs baseline: 1.1527x; 1.1527x over previous
#include <cuda_runtime.h>
#include <cstdint>

#define B_ 32
#define S_ 4096
#define K_ 1024
#define H_ 1024
#define V_ 1024

#define TM 256             // rows (b,s) per block
#define TN 128             // h columns per pass
#define NPASS (H_ / TN)    // 8
#define KCH 32             // k floats per chunk buffer
#define NCHUNK (K_ / KCH)  // 32
#define SSTR 40            // smem row stride in floats (32 data + 8 pad)
#define CSPLIT 32

#define A_FLOATS (TM * SSTR)
#define B_FLOATS (TN * SSTR)
#define DSMEM_BYTES ((2 * A_FLOATS + 2 * B_FLOATS) * 4)

// ---------------- scratch ----------------
__device__ float g_qproj[B_ * H_];
__device__ float g_scores[B_ * S_];
__device__ float g_ctx_part[CSPLIT * B_ * V_];

// ---------------- helpers ----------------
__device__ __forceinline__ void cpa16s(uint32_t s, const void* g) {
    asm volatile("cp.async.cg.shared.global [%0], [%1], 16;" :: "r"(s), "l"(g));
}
__device__ __forceinline__ void cp_commit() { asm volatile("cp.async.commit_group;"); }
template <int N> __device__ __forceinline__ void cp_wait() {
    asm volatile("cp.async.wait_group %0;" :: "n"(N));
}
__device__ __forceinline__ float tanh_mufu(float x) {
    float y;
    asm("tanh.approx.f32 %0, %1;" : "=f"(y) : "f"(x));
    return y;
}
// raw f32 bits fed as tf32 (hardware reads the tf32 field; no cvt needed)
__device__ __forceinline__ void mma_tf32(float c[4], uint32_t a0, uint32_t a1,
                                         uint32_t a2, uint32_t a3,
                                         uint32_t b0, uint32_t b1) {
    asm volatile(
        "mma.sync.aligned.m16n8k8.row.col.f32.tf32.tf32.f32 "
        "{%0,%1,%2,%3}, {%4,%5,%6,%7}, {%8,%9}, {%0,%1,%2,%3};"
        : "+f"(c[0]), "+f"(c[1]), "+f"(c[2]), "+f"(c[3])
        : "r"(a0), "r"(a1), "r"(a2), "r"(a3), "r"(b0), "r"(b1));
}

// ---------------- kernel 1: q_proj (fp32 exact, biases folded) ----------------
__global__ void qproj_kernel(const float* __restrict__ query,
                             const float* __restrict__ Wq_w,
                             const float* __restrict__ Wq_b,
                             const float* __restrict__ Wk_b) {
    __shared__ float q[K_];
    int b = blockIdx.x, hbase = blockIdx.y * 128;
    int tid = threadIdx.x;
    for (int i = tid; i < K_; i += 256) q[i] = query[b * K_ + i];
    __syncthreads();
    int warp = tid >> 5, lane = tid & 31;
    for (int i = 0; i < 16; i++) {
        int h = hbase + warp * 16 + i;
        const float* wr = Wq_w + (size_t)h * K_;
        float acc = 0.f;
        #pragma unroll 8
        for (int k = lane; k < K_; k += 32) acc += q[k] * wr[k];
        #pragma unroll
        for (int o = 16; o; o >>= 1) acc += __shfl_xor_sync(0xffffffffu, acc, o);
        if (lane == 0) g_qproj[b * H_ + h] = acc + Wq_b[h] + Wk_b[h];
    }
}

// ---------------- kernel 2: fused k_proj GEMM + tanh + v_w (tf32 mma.sync) -------
// 512 threads = 16 warps in 8(m) x 2(n) grid; warp tile 32x64; TM=256 x TN=128.
__global__ __launch_bounds__(512, 1) void scores_kernel(
    const float* __restrict__ keys, const float* __restrict__ Wk,
    const int* __restrict__ mask, const float* __restrict__ v_w) {
    extern __shared__ float dsm[];
    __shared__ float qs[TN];
    __shared__ float vs[TN];
    __shared__ float sscore[TM];

    float* As[2] = {dsm, dsm + A_FLOATS};
    float* Bs[2] = {dsm + 2 * A_FLOATS, dsm + 2 * A_FLOATS + B_FLOATS};
    uint32_t Aau[2], Bau[2];
    #pragma unroll
    for (int i = 0; i < 2; i++) {
        Aau[i] = (uint32_t)__cvta_generic_to_shared(As[i]);
        Bau[i] = (uint32_t)__cvta_generic_to_shared(Bs[i]);
    }

    int tid = threadIdx.x, warp = tid >> 5, lane = tid & 31;
    int wm = warp >> 1, wn = warp & 1;
    int t4 = lane & 3, q8 = lane >> 2;

    if (tid < TM) sscore[tid] = 0.f;

    int row0 = blockIdx.x * TM;
    int b = row0 >> 12;   // S_ = 4096
    const float* kb = keys + (size_t)row0 * K_;

    float sacc[4] = {0.f, 0.f, 0.f, 0.f};
    float c[2][8][4];

#define LOAD_CHUNK(bufi, wbase, col0)                                                 \
    do {                                                                              \
        _Pragma("unroll") for (int i = 0; i < 4; i++) {                               \
            int idx = i * 512 + tid;                                                  \
            int r = idx >> 3, u = idx & 7;                                            \
            cpa16s(Aau[bufi] + (uint32_t)(r * SSTR + u * 4) * 4u,                     \
                   kb + (size_t)r * K_ + (col0) + u * 4);                             \
        }                                                                             \
        _Pragma("unroll") for (int i = 0; i < 2; i++) {                               \
            int idx = i * 512 + tid;                                                  \
            int r = idx >> 3, u = idx & 7;                                            \
            cpa16s(Bau[bufi] + (uint32_t)(r * SSTR + u * 4) * 4u,                     \
                   (wbase) + (size_t)r * K_ + (col0) + u * 4);                        \
        }                                                                             \
    } while (0)

    for (int ht = 0; ht < NPASS; ht++) {
        int h0 = ht * TN;
        __syncthreads();  // prev epilogue done with qs/vs; covers sscore init
        if (tid < TN) {
            qs[tid] = g_qproj[b * H_ + h0 + tid];
            vs[tid] = v_w[h0 + tid];
        }
        const float* wb = Wk + (size_t)h0 * K_;

        #pragma unroll
        for (int mt = 0; mt < 2; mt++)
            #pragma unroll
            for (int nt = 0; nt < 8; nt++)
                #pragma unroll
                for (int j = 0; j < 4; j++) c[mt][nt][j] = 0.f;

        LOAD_CHUNK(0, wb, 0);
        cp_commit();

        for (int kc = 0; kc < NCHUNK; kc++) {
            int buf = kc & 1;
            if (kc + 1 < NCHUNK) {
                LOAD_CHUNK(buf ^ 1, wb, (kc + 1) * KCH);
                cp_commit();
                cp_wait<1>();
            } else {
                cp_wait<0>();
            }
            __syncthreads();

            const float* ks_ = As[buf];
            const float* ws_ = Bs[buf];
            #pragma unroll
            for (int ks = 0; ks < 4; ks++) {
                // permuted-k: thread t owns k-pair {2t, 2t+1} for BOTH A and B
                int c0 = ks * 8 + 2 * t4;
                uint2 a[2][2];
                int ar = wm * 32 + q8;
                #pragma unroll
                for (int mt = 0; mt < 2; mt++) {
                    int r = ar + mt * 16;
                    a[mt][0] = *(const uint2*)&ks_[r * SSTR + c0];
                    a[mt][1] = *(const uint2*)&ks_[(r + 8) * SSTR + c0];
                }
                uint2 bb[8];
                int bc = wn * 64 + q8;
                #pragma unroll
                for (int nt = 0; nt < 8; nt++)
                    bb[nt] = *(const uint2*)&ws_[(bc + nt * 8) * SSTR + c0];
                #pragma unroll
                for (int mt = 0; mt < 2; mt++)
                    #pragma unroll
                    for (int nt = 0; nt < 8; nt++)
                        mma_tf32(c[mt][nt], a[mt][0].x, a[mt][1].x,
                                 a[mt][0].y, a[mt][1].y, bb[nt].x, bb[nt].y);
            }
            __syncthreads();
        }

        // fused epilogue: sacc += tanh(c + q_proj) * v_w
        #pragma unroll
        for (int mt = 0; mt < 2; mt++) {
            #pragma unroll
            for (int nt = 0; nt < 8; nt++) {
                int col = wn * 64 + nt * 8 + t4 * 2;
                float q0 = qs[col], q1 = qs[col + 1];
                float v0 = vs[col], v1 = vs[col + 1];
                sacc[mt * 2 + 0] = fmaf(tanh_mufu(c[mt][nt][0] + q0), v0,
                                   fmaf(tanh_mufu(c[mt][nt][1] + q1), v1, sacc[mt * 2 + 0]));
                sacc[mt * 2 + 1] = fmaf(tanh_mufu(c[mt][nt][2] + q0), v0,
                                   fmaf(tanh_mufu(c[mt][nt][3] + q1), v1, sacc[mt * 2 + 1]));
            }
        }
    }

    // quad reduce (lane&3 spans each n-tile's 8 columns)
    #pragma unroll
    for (int i = 0; i < 4; i++) {
        sacc[i] += __shfl_xor_sync(0xffffffffu, sacc[i], 1);
        sacc[i] += __shfl_xor_sync(0xffffffffu, sacc[i], 2);
    }
    __syncthreads();
    if (t4 == 0) {
        int r = wm * 32 + q8;
        atomicAdd(&sscore[r],      sacc[0]);
        atomicAdd(&sscore[r + 8],  sacc[1]);
        atomicAdd(&sscore[r + 16], sacc[2]);
        atomicAdd(&sscore[r + 24], sacc[3]);
    }
    __syncthreads();
    if (tid < TM) {
        int srow = row0 + tid;
        g_scores[srow] = (mask[srow] == 0) ? __int_as_float(0xff800000) : sscore[tid];
    }
#undef LOAD_CHUNK
}

// ---------------- kernel 3: masked softmax ----------------
__global__ void softmax_kernel(float* __restrict__ w_out) {
    __shared__ float red[8];
    __shared__ float bval;
    int b = blockIdx.x, tid = threadIdx.x;
    int warp = tid >> 5, lane = tid & 31;
    const float* sc = g_scores + b * S_;

    float m = __int_as_float(0xff800000);
    for (int s = tid; s < S_; s += 256) m = fmaxf(m, sc[s]);
    #pragma unroll
    for (int o = 16; o; o >>= 1) m = fmaxf(m, __shfl_xor_sync(0xffffffffu, m, o));
    if (lane == 0) red[warp] = m;
    __syncthreads();
    if (warp == 0) {
        float v = (lane < 8) ? red[lane] : __int_as_float(0xff800000);
        #pragma unroll
        for (int o = 4; o; o >>= 1) v = fmaxf(v, __shfl_xor_sync(0xffffffffu, v, o));
        if (lane == 0) bval = v;
    }
    __syncthreads();
    float mm = bval;

    float sum = 0.f;
    float* wbuf = w_out + b * S_;
    for (int s = tid; s < S_; s += 256) {
        float e = expf(sc[s] - mm);
        wbuf[s] = e;
        sum += e;
    }
    #pragma unroll
    for (int o = 16; o; o >>= 1) sum += __shfl_xor_sync(0xffffffffu, sum, o);
    if (lane == 0) red[warp] = sum;
    __syncthreads();
    if (warp == 0) {
        float v = (lane < 8) ? red[lane] : 0.f;
        #pragma unroll
        for (int o = 4; o; o >>= 1) v += __shfl_xor_sync(0xffffffffu, v, o);
        if (lane == 0) bval = v;
    }
    __syncthreads();
    float inv = 1.0f / bval;
    for (int s = tid; s < S_; s += 256) wbuf[s] *= inv;
}

// ---------------- kernel 4: context = attn @ values (split-S x32) ----------------
__global__ void context_part_kernel(const float* __restrict__ values,
                                    const float* __restrict__ w) {
    int b = blockIdx.x >> 5;
    int p = blockIdx.x & 31;
    int tid = threadIdx.x;
    int s0 = p * (S_ / CSPLIT);  // 128 rows per split
    const float4* vp = (const float4*)(values + ((size_t)b * S_ + s0) * V_) + tid;
    const float* wb = w + b * S_ + s0;
    float4 acc = make_float4(0.f, 0.f, 0.f, 0.f);
    #pragma unroll 8
    for (int s = 0; s < S_ / CSPLIT; s++) {
        float ws = __ldg(wb + s);
        float4 v = __ldg(vp + (size_t)s * (V_ / 4));
        acc.x += ws * v.x; acc.y += ws * v.y; acc.z += ws * v.z; acc.w += ws * v.w;
    }
    ((float4*)g_ctx_part)[((size_t)p * B_ + b) * (V_ / 4) + tid] = acc;
}

__global__ void context_reduce_kernel(float* __restrict__ ctx) {
    int b = blockIdx.x, tid = threadIdx.x;
    for (int i = tid; i < V_; i += 256) {
        float s = 0.f;
        #pragma unroll
        for (int p = 0; p < CSPLIT; p++) s += g_ctx_part[((size_t)p * B_ + b) * V_ + i];
        ctx[b * V_ + i] = s;
    }
}

// ---------------- launch ----------------
extern "C" void kernel_launch(void* const* d_in, const int* in_sizes, int n_in,
                              void* d_out, int out_size) {
    const float* query  = (const float*)d_in[0];
    const float* keys   = (const float*)d_in[1];
    const float* values = (const float*)d_in[2];
    const int*   mask   = (const int*)d_in[3];
    const float* Wq_w   = (const float*)d_in[4];
    const float* Wq_b   = (const float*)d_in[5];
    const float* Wk_w   = (const float*)d_in[6];
    const float* Wk_b   = (const float*)d_in[7];
    const float* v_w    = (const float*)d_in[8];
    (void)in_sizes; (void)n_in; (void)out_size;

    float* out     = (float*)d_out;
    float* out_ctx = out;             // context: [32,1024]
    float* out_w   = out + B_ * V_;   // attention_weights: [32,4096]

    cudaFuncSetAttribute(scores_kernel,
                         cudaFuncAttributeMaxDynamicSharedMemorySize, DSMEM_BYTES);

    qproj_kernel<<<dim3(B_, H_ / 128), 256>>>(query, Wq_w, Wq_b, Wk_b);
    scores_kernel<<<(B_ * S_) / TM, 512, DSMEM_BYTES>>>(keys, Wk_w, mask, v_w);
    softmax_kernel<<<B_, 256>>>(out_w);
    context_part_kernel<<<B_ * CSPLIT, 256>>>(values, out_w);
    context_reduce_kernel<<<B_, 256>>>(out_ctx);
}

// round 4
// speedup vs baseline: 3.1453x; 2.7286x over previous
#include <cuda_runtime.h>
#include <cuda_fp16.h>
#include <cstdint>

#define B_ 32
#define S_ 4096
#define K_ 1024
#define H_ 1024
#define V_ 1024

#define TM 128             // compacted rows per block
#define TN 256             // h columns per pass
#define NPASS (H_ / TN)    // 4
#define KCH 32             // k floats per chunk buffer
#define NCHUNK (K_ / KCH)  // 32
#define SSTR 40            // smem row stride in floats (32 data + 8 pad)
#define CSPLIT 32
#define TILES_PER_B (S_ / TM)  // 32

#define A_FLOATS (TM * SSTR)   // 5120
#define B_FLOATS (TN * SSTR)   // 10240
#define DSMEM_BYTES ((2 * A_FLOATS + 2 * B_FLOATS) * 4)  // 120 KB

// ---------------- scratch ----------------
__device__ float g_qproj[B_ * H_];
__device__ float g_scores[B_ * S_];
__device__ float g_ctx_part[CSPLIT * B_ * V_];
__device__ int   g_idx[B_ * S_];   // compacted unmasked row indices per batch
__device__ int   g_cnt[B_];        // unmasked count per batch

// ---------------- helpers ----------------
__device__ __forceinline__ void cpa16s(uint32_t s, const void* g) {
    asm volatile("cp.async.cg.shared.global [%0], [%1], 16;" :: "r"(s), "l"(g));
}
__device__ __forceinline__ void cp_commit() { asm volatile("cp.async.commit_group;"); }
template <int N> __device__ __forceinline__ void cp_wait() {
    asm volatile("cp.async.wait_group %0;" :: "n"(N));
}
__device__ __forceinline__ float tanh_mufu(float x) {
    float y;
    asm("tanh.approx.f32 %0, %1;" : "=f"(y) : "f"(x));
    return y;
}
__device__ __forceinline__ uint32_t h2pack(float2 v) {
    __half2 h = __floats2half2_rn(v.x, v.y);
    return *(uint32_t*)&h;
}
__device__ __forceinline__ void mma16816(float c[4], const uint32_t a[4],
                                         const uint32_t b[2]) {
    asm volatile(
        "mma.sync.aligned.m16n8k16.row.col.f32.f16.f16.f32 "
        "{%0,%1,%2,%3}, {%4,%5,%6,%7}, {%8,%9}, {%0,%1,%2,%3};"
        : "+f"(c[0]), "+f"(c[1]), "+f"(c[2]), "+f"(c[3])
        : "r"(a[0]), "r"(a[1]), "r"(a[2]), "r"(a[3]), "r"(b[0]), "r"(b[1]));
}

// ---------------- kernel 0: init scores=-inf, counters=0 ----------------
__global__ void init_kernel() {
    int i = blockIdx.x * 1024 + threadIdx.x;
    g_scores[i] = __int_as_float(0xff800000);
    if (blockIdx.x == 0 && threadIdx.x < B_) g_cnt[threadIdx.x] = 0;
}

// ---------------- kernel 0b: compact unmasked row indices ----------------
__global__ void compact_kernel(const int* __restrict__ mask) {
    int b = blockIdx.x, tid = threadIdx.x, lane = tid & 31;
    const int* mb = mask + b * S_;
    for (int it = 0; it < S_ / 256; it++) {
        int s = it * 256 + tid;
        int m = (mb[s] != 0);
        unsigned bal = __ballot_sync(0xffffffffu, m);
        int pre = __popc(bal & ((1u << lane) - 1));
        int tot = __popc(bal);
        int base;
        if (lane == 0) base = atomicAdd(&g_cnt[b], tot);
        base = __shfl_sync(0xffffffffu, base, 0);
        if (m) g_idx[b * S_ + base + pre] = s;
    }
}

// ---------------- kernel 1: q_proj (fp32 exact, biases folded) ----------------
__global__ void qproj_kernel(const float* __restrict__ query,
                             const float* __restrict__ Wq_w,
                             const float* __restrict__ Wq_b,
                             const float* __restrict__ Wk_b) {
    __shared__ float q[K_];
    int b = blockIdx.x, hbase = blockIdx.y * 128;
    int tid = threadIdx.x;
    for (int i = tid; i < K_; i += 256) q[i] = query[b * K_ + i];
    __syncthreads();
    int warp = tid >> 5, lane = tid & 31;
    for (int i = 0; i < 16; i++) {
        int h = hbase + warp * 16 + i;
        const float* wr = Wq_w + (size_t)h * K_;
        float acc = 0.f;
        #pragma unroll 8
        for (int k = lane; k < K_; k += 32) acc += q[k] * wr[k];
        #pragma unroll
        for (int o = 16; o; o >>= 1) acc += __shfl_xor_sync(0xffffffffu, acc, o);
        if (lane == 0) g_qproj[b * H_ + h] = acc + Wq_b[h] + Wk_b[h];
    }
}

// ---------------- kernel 2: fused k_proj + tanh + v_w on UNMASKED rows --------
// 512 threads = 16 warps in 4(m) x 4(n) grid; warp tile 32x64; TM=128 x TN=256.
// fp16 m16n8k16 MMAs, f32 accum; A rows gathered via compacted index list.
__global__ __launch_bounds__(512, 1) void scores_kernel(
    const float* __restrict__ keys, const float* __restrict__ Wk,
    const float* __restrict__ v_w) {
    extern __shared__ float dsm[];
    __shared__ int   ridx[TM];
    __shared__ float qs[TN];
    __shared__ float vs[TN];
    __shared__ float sscore[TM];

    int bidx = blockIdx.x;
    int b = bidx / TILES_PER_B;
    int t = bidx % TILES_PER_B;
    int cnt = g_cnt[b];
    if (t * TM >= cnt) return;

    float* As[2] = {dsm, dsm + A_FLOATS};
    float* Bs[2] = {dsm + 2 * A_FLOATS, dsm + 2 * A_FLOATS + B_FLOATS};
    uint32_t Aau[2], Bau[2];
    #pragma unroll
    for (int i = 0; i < 2; i++) {
        Aau[i] = (uint32_t)__cvta_generic_to_shared(As[i]);
        Bau[i] = (uint32_t)__cvta_generic_to_shared(Bs[i]);
    }

    int tid = threadIdx.x, warp = tid >> 5, lane = tid & 31;
    int wm = warp >> 2, wn = warp & 3;     // 4x4 warp grid
    int t4 = lane & 3, q8 = lane >> 2;

    if (tid < TM) {
        int j = t * TM + tid;
        ridx[tid] = g_idx[b * S_ + (j < cnt ? j : cnt - 1)];
        sscore[tid] = 0.f;
    }
    __syncthreads();

    const float* kb = keys + (size_t)b * S_ * K_;
    // per-thread A row pointers (constant across chunks & passes)
    const float* arow[2];
    int u8 = tid & 7;  // float4 slot within 32-float chunk row
    #pragma unroll
    for (int i = 0; i < 2; i++)
        arow[i] = kb + (size_t)ridx[i * 64 + (tid >> 3)] * K_;

    float sacc[4] = {0.f, 0.f, 0.f, 0.f};
    float c[2][8][4];

#define LOAD_CHUNK(bufi, col0)                                                  \
    do {                                                                        \
        _Pragma("unroll") for (int i = 0; i < 2; i++) {                         \
            int r = i * 64 + (tid >> 3);                                        \
            cpa16s(Aau[bufi] + (uint32_t)(r * SSTR + u8 * 4) * 4u,              \
                   arow[i] + (col0) + u8 * 4);                                  \
        }                                                                       \
        _Pragma("unroll") for (int i = 0; i < 4; i++) {                         \
            int r = i * 64 + (tid >> 3);                                        \
            cpa16s(Bau[bufi] + (uint32_t)(r * SSTR + u8 * 4) * 4u,              \
                   brow[i] + (col0) + u8 * 4);                                  \
        }                                                                       \
    } while (0)

    for (int ht = 0; ht < NPASS; ht++) {
        int h0 = ht * TN;
        __syncthreads();  // prev epilogue done with qs/vs
        if (tid < TN) {
            qs[tid] = g_qproj[b * H_ + h0 + tid];
            vs[tid] = v_w[h0 + tid];
        }
        const float* brow[4];
        #pragma unroll
        for (int i = 0; i < 4; i++)
            brow[i] = Wk + (size_t)(h0 + i * 64 + (tid >> 3)) * K_;

        #pragma unroll
        for (int mt = 0; mt < 2; mt++)
            #pragma unroll
            for (int nt = 0; nt < 8; nt++)
                #pragma unroll
                for (int j = 0; j < 4; j++) c[mt][nt][j] = 0.f;

        LOAD_CHUNK(0, 0);
        cp_commit();

        for (int kc = 0; kc < NCHUNK; kc++) {
            int buf = kc & 1;
            if (kc + 1 < NCHUNK) {
                LOAD_CHUNK(buf ^ 1, (kc + 1) * KCH);
                cp_commit();
                cp_wait<1>();
            } else {
                cp_wait<0>();
            }
            __syncthreads();

            const float* ks_ = As[buf];
            const float* ws_ = Bs[buf];
            #pragma unroll
            for (int ks = 0; ks < 2; ks++) {
                int c0 = ks * 16 + 2 * t4;
                uint32_t a[2][4];
                #pragma unroll
                for (int mt = 0; mt < 2; mt++) {
                    int r = wm * 32 + mt * 16 + q8;
                    a[mt][0] = h2pack(*(const float2*)&ks_[r * SSTR + c0]);
                    a[mt][1] = h2pack(*(const float2*)&ks_[(r + 8) * SSTR + c0]);
                    a[mt][2] = h2pack(*(const float2*)&ks_[r * SSTR + c0 + 8]);
                    a[mt][3] = h2pack(*(const float2*)&ks_[(r + 8) * SSTR + c0 + 8]);
                }
                uint32_t bb[8][2];
                #pragma unroll
                for (int nt = 0; nt < 8; nt++) {
                    int col = wn * 64 + nt * 8 + q8;
                    bb[nt][0] = h2pack(*(const float2*)&ws_[col * SSTR + c0]);
                    bb[nt][1] = h2pack(*(const float2*)&ws_[col * SSTR + c0 + 8]);
                }
                #pragma unroll
                for (int mt = 0; mt < 2; mt++)
                    #pragma unroll
                    for (int nt = 0; nt < 8; nt++)
                        mma16816(c[mt][nt], a[mt], bb[nt]);
            }
            __syncthreads();
        }

        // fused epilogue: sacc += tanh(c + q_proj) * v_w
        #pragma unroll
        for (int mt = 0; mt < 2; mt++) {
            #pragma unroll
            for (int nt = 0; nt < 8; nt++) {
                int col = wn * 64 + nt * 8 + t4 * 2;
                float q0 = qs[col], q1 = qs[col + 1];
                float v0 = vs[col], v1 = vs[col + 1];
                sacc[mt * 2 + 0] = fmaf(tanh_mufu(c[mt][nt][0] + q0), v0,
                                   fmaf(tanh_mufu(c[mt][nt][1] + q1), v1, sacc[mt * 2 + 0]));
                sacc[mt * 2 + 1] = fmaf(tanh_mufu(c[mt][nt][2] + q0), v0,
                                   fmaf(tanh_mufu(c[mt][nt][3] + q1), v1, sacc[mt * 2 + 1]));
            }
        }
    }

    // quad reduce (lane&3 spans each n-tile's 8 columns)
    #pragma unroll
    for (int i = 0; i < 4; i++) {
        sacc[i] += __shfl_xor_sync(0xffffffffu, sacc[i], 1);
        sacc[i] += __shfl_xor_sync(0xffffffffu, sacc[i], 2);
    }
    __syncthreads();
    if (t4 == 0) {
        int r = wm * 32 + q8;
        atomicAdd(&sscore[r],      sacc[0]);
        atomicAdd(&sscore[r + 8],  sacc[1]);
        atomicAdd(&sscore[r + 16], sacc[2]);
        atomicAdd(&sscore[r + 24], sacc[3]);
    }
    __syncthreads();
    if (tid < TM) {
        int j = t * TM + tid;
        if (j < cnt) g_scores[b * S_ + ridx[tid]] = sscore[tid];
    }
#undef LOAD_CHUNK
}

// ---------------- kernel 3: masked softmax ----------------
__global__ void softmax_kernel(float* __restrict__ w_out) {
    __shared__ float red[8];
    __shared__ float bval;
    int b = blockIdx.x, tid = threadIdx.x;
    int warp = tid >> 5, lane = tid & 31;
    const float* sc = g_scores + b * S_;

    float m = __int_as_float(0xff800000);
    for (int s = tid; s < S_; s += 256) m = fmaxf(m, sc[s]);
    #pragma unroll
    for (int o = 16; o; o >>= 1) m = fmaxf(m, __shfl_xor_sync(0xffffffffu, m, o));
    if (lane == 0) red[warp] = m;
    __syncthreads();
    if (warp == 0) {
        float v = (lane < 8) ? red[lane] : __int_as_float(0xff800000);
        #pragma unroll
        for (int o = 4; o; o >>= 1) v = fmaxf(v, __shfl_xor_sync(0xffffffffu, v, o));
        if (lane == 0) bval = v;
    }
    __syncthreads();
    float mm = bval;

    float sum = 0.f;
    float* wbuf = w_out + b * S_;
    for (int s = tid; s < S_; s += 256) {
        float e = expf(sc[s] - mm);
        wbuf[s] = e;
        sum += e;
    }
    #pragma unroll
    for (int o = 16; o; o >>= 1) sum += __shfl_xor_sync(0xffffffffu, sum, o);
    if (lane == 0) red[warp] = sum;
    __syncthreads();
    if (warp == 0) {
        float v = (lane < 8) ? red[lane] : 0.f;
        #pragma unroll
        for (int o = 4; o; o >>= 1) v += __shfl_xor_sync(0xffffffffu, v, o);
        if (lane == 0) bval = v;
    }
    __syncthreads();
    float inv = 1.0f / bval;
    for (int s = tid; s < S_; s += 256) wbuf[s] *= inv;
}

// ---------------- kernel 4: context = attn @ values (split-S, skip w==0) -------
__global__ void context_part_kernel(const float* __restrict__ values,
                                    const float* __restrict__ w) {
    int b = blockIdx.x >> 5;
    int p = blockIdx.x & 31;
    int tid = threadIdx.x;
    int s0 = p * (S_ / CSPLIT);  // 128 rows per split
    const float4* vp = (const float4*)(values + ((size_t)b * S_ + s0) * V_) + tid;
    const float* wb = w + b * S_ + s0;
    float4 acc = make_float4(0.f, 0.f, 0.f, 0.f);
    for (int s = 0; s < S_ / CSPLIT; s++) {
        float ws = __ldg(wb + s);
        if (ws != 0.f) {  // masked rows have weight exactly 0 -> skip values read
            float4 v = __ldg(vp + (size_t)s * (V_ / 4));
            acc.x += ws * v.x; acc.y += ws * v.y;
            acc.z += ws * v.z; acc.w += ws * v.w;
        }
    }
    ((float4*)g_ctx_part)[((size_t)p * B_ + b) * (V_ / 4) + tid] = acc;
}

__global__ void context_reduce_kernel(float* __restrict__ ctx) {
    int b = blockIdx.x, tid = threadIdx.x;
    for (int i = tid; i < V_; i += 256) {
        float s = 0.f;
        #pragma unroll
        for (int p = 0; p < CSPLIT; p++) s += g_ctx_part[((size_t)p * B_ + b) * V_ + i];
        ctx[b * V_ + i] = s;
    }
}

// ---------------- launch ----------------
extern "C" void kernel_launch(void* const* d_in, const int* in_sizes, int n_in,
                              void* d_out, int out_size) {
    const float* query  = (const float*)d_in[0];
    const float* keys   = (const float*)d_in[1];
    const float* values = (const float*)d_in[2];
    const int*   mask   = (const int*)d_in[3];
    const float* Wq_w   = (const float*)d_in[4];
    const float* Wq_b   = (const float*)d_in[5];
    const float* Wk_w   = (const float*)d_in[6];
    const float* Wk_b   = (const float*)d_in[7];
    const float* v_w    = (const float*)d_in[8];
    (void)in_sizes; (void)n_in; (void)out_size;

    float* out     = (float*)d_out;
    float* out_ctx = out;             // context: [32,1024]
    float* out_w   = out + B_ * V_;   // attention_weights: [32,4096]

    cudaFuncSetAttribute(scores_kernel,
                         cudaFuncAttributeMaxDynamicSharedMemorySize, DSMEM_BYTES);

    init_kernel<<<(B_ * S_) / 1024, 1024>>>();
    compact_kernel<<<B_, 256>>>(mask);
    qproj_kernel<<<dim3(B_, H_ / 128), 256>>>(query, Wq_w, Wq_b, Wk_b);
    scores_kernel<<<B_ * TILES_PER_B, 512, DSMEM_BYTES>>>(keys, Wk_w, v_w);
    softmax_kernel<<<B_, 256>>>(out_w);
    context_part_kernel<<<B_ * CSPLIT, 256>>>(values, out_w);
    context_reduce_kernel<<<B_, 256>>>(out_ctx);
}

// round 5
// speedup vs baseline: 4.4862x; 1.4263x over previous
#include <cuda_runtime.h>
#include <cuda_fp16.h>
#include <cstdint>

#define B_ 32
#define S_ 4096
#define K_ 1024
#define H_ 1024
#define V_ 1024

#define TM 128             // compacted rows per block
#define TN 256             // h columns per pass
#define NPASS (H_ / TN)    // 4
#define KCH 64             // k halves per chunk (128B rows)
#define NCHUNK (K_ / KCH)  // 16
#define SSTRH 72           // smem row stride in halves (64 data + 8 pad = 144B)
#define CSPLIT 32
#define TILES_PER_B (S_ / TM)  // 32

#define A_HALFS (TM * SSTRH)   // 9216
#define B_HALFS (TN * SSTRH)   // 18432
#define DSMEM_BYTES ((2 * A_HALFS + 2 * B_HALFS) * 2)  // 110592 B

// ---------------- scratch ----------------
__device__ float  g_qproj[B_ * H_];
__device__ float  g_scores[B_ * S_];
__device__ float  g_ctx_part[CSPLIT * B_ * V_];
__device__ int    g_idx[B_ * S_];       // compacted unmasked row indices
__device__ int    g_cnt[B_];            // unmasked count per batch
__device__ __half g_keys_h[B_ * S_ * K_];  // gathered fp16 keys (compacted rows)
__device__ __half g_wk_h[H_ * K_];         // fp16 Wk

// ---------------- helpers ----------------
__device__ __forceinline__ void cpa16s(uint32_t s, const void* g) {
    asm volatile("cp.async.cg.shared.global [%0], [%1], 16;" :: "r"(s), "l"(g));
}
__device__ __forceinline__ void cp_commit() { asm volatile("cp.async.commit_group;"); }
template <int N> __device__ __forceinline__ void cp_wait() {
    asm volatile("cp.async.wait_group %0;" :: "n"(N));
}
__device__ __forceinline__ float tanh_mufu(float x) {
    float y;
    asm("tanh.approx.f32 %0, %1;" : "=f"(y) : "f"(x));
    return y;
}
__device__ __forceinline__ void ldsm_x4(uint32_t r[4], uint32_t addr) {
    asm volatile("ldmatrix.sync.aligned.m8n8.x4.shared.b16 {%0,%1,%2,%3}, [%4];"
                 : "=r"(r[0]), "=r"(r[1]), "=r"(r[2]), "=r"(r[3]) : "r"(addr));
}
__device__ __forceinline__ void mma16816(float c[4], const uint32_t a[4],
                                         uint32_t b0, uint32_t b1) {
    asm volatile(
        "mma.sync.aligned.m16n8k16.row.col.f32.f16.f16.f32 "
        "{%0,%1,%2,%3}, {%4,%5,%6,%7}, {%8,%9}, {%0,%1,%2,%3};"
        : "+f"(c[0]), "+f"(c[1]), "+f"(c[2]), "+f"(c[3])
        : "r"(a[0]), "r"(a[1]), "r"(a[2]), "r"(a[3]), "r"(b0), "r"(b1));
}
__device__ __forceinline__ void pack8h(__half* dst, const float4 a, const float4 b) {
    __half2* d = (__half2*)dst;
    d[0] = __floats2half2_rn(a.x, a.y);
    d[1] = __floats2half2_rn(a.z, a.w);
    d[2] = __floats2half2_rn(b.x, b.y);
    d[3] = __floats2half2_rn(b.z, b.w);
}

// ---------------- kernel 0: init scores=-inf, counters=0 ----------------
__global__ void init_kernel() {
    int i = blockIdx.x * 1024 + threadIdx.x;
    g_scores[i] = __int_as_float(0xff800000);
    if (blockIdx.x == 0 && threadIdx.x < B_) g_cnt[threadIdx.x] = 0;
}

// ---------------- kernel 0b: compact unmasked row indices ----------------
__global__ void compact_kernel(const int* __restrict__ mask) {
    int b = blockIdx.x, tid = threadIdx.x, lane = tid & 31;
    const int* mb = mask + b * S_;
    for (int it = 0; it < S_ / 256; it++) {
        int s = it * 256 + tid;
        int m = (mb[s] != 0);
        unsigned bal = __ballot_sync(0xffffffffu, m);
        int pre = __popc(bal & ((1u << lane) - 1));
        int tot = __popc(bal);
        int base;
        if (lane == 0) base = atomicAdd(&g_cnt[b], tot);
        base = __shfl_sync(0xffffffffu, base, 0);
        if (m) g_idx[b * S_ + base + pre] = s;
    }
}

// ---------------- kernel 0c: gather unmasked keys rows -> fp16 compacted --------
__global__ void gather_keys_kernel(const float* __restrict__ keys) {
    int b = blockIdx.x / TILES_PER_B;
    int t = blockIdx.x % TILES_PER_B;
    int cnt = g_cnt[b];
    if (t * TM >= cnt) return;
    int tid = threadIdx.x;
    // 128 rows x 128 groups (8 halves each) per block
    for (int idx = tid; idx < TM * (K_ / 8); idx += 256) {
        int j = t * TM + (idx >> 7);          // compacted row
        if (j >= cnt) break;
        int u = idx & 127;                    // 8-half group
        int src = g_idx[b * S_ + j];
        const float4* sp = (const float4*)(keys + ((size_t)b * S_ + src) * K_ + u * 8);
        __half hv[8];
        pack8h(hv, sp[0], sp[1]);
        *(uint4*)(g_keys_h + ((size_t)b * S_ + j) * K_ + u * 8) = *(uint4*)hv;
    }
}

// ---------------- kernel 0d: Wk -> fp16 ----------------
__global__ void convert_wk_kernel(const float* __restrict__ Wk) {
    int i = blockIdx.x * 256 + threadIdx.x;   // one 8-elem group each
    const float4* sp = (const float4*)(Wk + (size_t)i * 8);
    __half hv[8];
    pack8h(hv, sp[0], sp[1]);
    *(uint4*)(g_wk_h + (size_t)i * 8) = *(uint4*)hv;
}

// ---------------- kernel 1: q_proj (fp32 exact, biases folded) ----------------
__global__ void qproj_kernel(const float* __restrict__ query,
                             const float* __restrict__ Wq_w,
                             const float* __restrict__ Wq_b,
                             const float* __restrict__ Wk_b) {
    __shared__ float q[K_];
    int b = blockIdx.x, hbase = blockIdx.y * 128;
    int tid = threadIdx.x;
    for (int i = tid; i < K_; i += 256) q[i] = query[b * K_ + i];
    __syncthreads();
    int warp = tid >> 5, lane = tid & 31;
    for (int i = 0; i < 16; i++) {
        int h = hbase + warp * 16 + i;
        const float* wr = Wq_w + (size_t)h * K_;
        float acc = 0.f;
        #pragma unroll 8
        for (int k = lane; k < K_; k += 32) acc += q[k] * wr[k];
        #pragma unroll
        for (int o = 16; o; o >>= 1) acc += __shfl_xor_sync(0xffffffffu, acc, o);
        if (lane == 0) g_qproj[b * H_ + h] = acc + Wq_b[h] + Wk_b[h];
    }
}

// ---------------- kernel 2: fused k_proj + tanh + v_w, fp16 LDSM mainloop -------
// 512 threads = 16 warps in 4(m) x 4(n) grid; warp tile 32x64; TM=128 x TN=256.
__global__ __launch_bounds__(512, 1) void scores_kernel(const float* __restrict__ v_w) {
    extern __shared__ __half dsmh[];
    __shared__ float qs[TN];
    __shared__ float vs[TN];
    __shared__ float sscore[TM];

    int bidx = blockIdx.x;
    int b = bidx / TILES_PER_B;
    int t = bidx % TILES_PER_B;
    int cnt = g_cnt[b];
    if (t * TM >= cnt) return;

    uint32_t Aau[2], Bau[2];
    Aau[0] = (uint32_t)__cvta_generic_to_shared(dsmh);
    Aau[1] = Aau[0] + A_HALFS * 2;
    Bau[0] = Aau[0] + 2 * A_HALFS * 2;
    Bau[1] = Bau[0] + B_HALFS * 2;

    int tid = threadIdx.x, warp = tid >> 5, lane = tid & 31;
    int wm = warp >> 2, wn = warp & 3;     // 4x4 warp grid
    int t4 = lane & 3, q8 = lane >> 2;
    int u8 = tid & 7;                      // 16B granule slot within 128B row

    if (tid < TM) sscore[tid] = 0.f;

    // per-thread source row pointers (compacted half keys; clamp handled by gather)
    int jrow[2];
    #pragma unroll
    for (int i = 0; i < 2; i++) {
        int j = t * TM + i * 64 + (tid >> 3);
        jrow[i] = (j < cnt) ? j : cnt - 1;
    }
    const __half* arow[2];
    #pragma unroll
    for (int i = 0; i < 2; i++)
        arow[i] = g_keys_h + ((size_t)b * S_ + jrow[i]) * K_;

    // ldmatrix per-thread base addresses (bytes)
    uint32_t a_lm = (uint32_t)((wm * 32 + (lane & 15)) * SSTRH + (lane >> 4) * 8) * 2u;
    uint32_t b_lm = (uint32_t)((wn * 64 + (lane & 7) + ((lane >> 4) << 3)) * SSTRH +
                               ((lane >> 3) & 1) * 8) * 2u;

    float sacc[4] = {0.f, 0.f, 0.f, 0.f};
    float c[2][8][4];

#define LOAD_CHUNK(bufi, col0)                                                  \
    do {                                                                        \
        _Pragma("unroll") for (int i = 0; i < 2; i++) {                         \
            int r = i * 64 + (tid >> 3);                                        \
            cpa16s(Aau[bufi] + (uint32_t)(r * SSTRH + u8 * 8) * 2u,             \
                   arow[i] + (col0) + u8 * 8);                                  \
        }                                                                       \
        _Pragma("unroll") for (int i = 0; i < 4; i++) {                         \
            int r = i * 64 + (tid >> 3);                                        \
            cpa16s(Bau[bufi] + (uint32_t)(r * SSTRH + u8 * 8) * 2u,             \
                   brow[i] + (col0) + u8 * 8);                                  \
        }                                                                       \
    } while (0)

    for (int ht = 0; ht < NPASS; ht++) {
        int h0 = ht * TN;
        __syncthreads();  // prev epilogue done with qs/vs
        if (tid < TN) {
            qs[tid] = g_qproj[b * H_ + h0 + tid];
            vs[tid] = v_w[h0 + tid];
        }
        const __half* brow[4];
        #pragma unroll
        for (int i = 0; i < 4; i++)
            brow[i] = g_wk_h + (size_t)(h0 + i * 64 + (tid >> 3)) * K_;

        #pragma unroll
        for (int mt = 0; mt < 2; mt++)
            #pragma unroll
            for (int nt = 0; nt < 8; nt++)
                #pragma unroll
                for (int j = 0; j < 4; j++) c[mt][nt][j] = 0.f;

        LOAD_CHUNK(0, 0);
        cp_commit();

        for (int kc = 0; kc < NCHUNK; kc++) {
            int buf = kc & 1;
            if (kc + 1 < NCHUNK) {
                LOAD_CHUNK(buf ^ 1, (kc + 1) * KCH);
                cp_commit();
                cp_wait<1>();
            } else {
                cp_wait<0>();
            }
            __syncthreads();

            #pragma unroll
            for (int kst = 0; kst < 4; kst++) {
                uint32_t koffB = (uint32_t)(kst * 16) * 2u;
                uint32_t a[2][4];
                ldsm_x4(a[0], Aau[buf] + a_lm + koffB);
                ldsm_x4(a[1], Aau[buf] + a_lm + (uint32_t)(16 * SSTRH) * 2u + koffB);
                uint32_t bf[4][4];
                #pragma unroll
                for (int p = 0; p < 4; p++)
                    ldsm_x4(bf[p], Bau[buf] + b_lm +
                                   (uint32_t)(p * 16 * SSTRH) * 2u + koffB);
                #pragma unroll
                for (int mt = 0; mt < 2; mt++)
                    #pragma unroll
                    for (int nt = 0; nt < 8; nt++)
                        mma16816(c[mt][nt], a[mt],
                                 bf[nt >> 1][(nt & 1) * 2],
                                 bf[nt >> 1][(nt & 1) * 2 + 1]);
            }
            __syncthreads();
        }

        // fused epilogue: sacc += tanh(c + q_proj) * v_w
        #pragma unroll
        for (int mt = 0; mt < 2; mt++) {
            #pragma unroll
            for (int nt = 0; nt < 8; nt++) {
                int col = wn * 64 + nt * 8 + t4 * 2;
                float q0 = qs[col], q1 = qs[col + 1];
                float v0 = vs[col], v1 = vs[col + 1];
                sacc[mt * 2 + 0] = fmaf(tanh_mufu(c[mt][nt][0] + q0), v0,
                                   fmaf(tanh_mufu(c[mt][nt][1] + q1), v1, sacc[mt * 2 + 0]));
                sacc[mt * 2 + 1] = fmaf(tanh_mufu(c[mt][nt][2] + q0), v0,
                                   fmaf(tanh_mufu(c[mt][nt][3] + q1), v1, sacc[mt * 2 + 1]));
            }
        }
    }

    // quad reduce (lane&3 spans each n-tile's 8 columns)
    #pragma unroll
    for (int i = 0; i < 4; i++) {
        sacc[i] += __shfl_xor_sync(0xffffffffu, sacc[i], 1);
        sacc[i] += __shfl_xor_sync(0xffffffffu, sacc[i], 2);
    }
    __syncthreads();
    if (t4 == 0) {
        int r = wm * 32 + q8;
        atomicAdd(&sscore[r],      sacc[0]);
        atomicAdd(&sscore[r + 8],  sacc[1]);
        atomicAdd(&sscore[r + 16], sacc[2]);
        atomicAdd(&sscore[r + 24], sacc[3]);
    }
    __syncthreads();
    if (tid < TM) {
        int j = t * TM + tid;
        if (j < cnt) g_scores[b * S_ + g_idx[b * S_ + j]] = sscore[tid];
    }
#undef LOAD_CHUNK
}

// ---------------- kernel 3: masked softmax ----------------
__global__ void softmax_kernel(float* __restrict__ w_out) {
    __shared__ float red[8];
    __shared__ float bval;
    int b = blockIdx.x, tid = threadIdx.x;
    int warp = tid >> 5, lane = tid & 31;
    const float* sc = g_scores + b * S_;

    float m = __int_as_float(0xff800000);
    for (int s = tid; s < S_; s += 256) m = fmaxf(m, sc[s]);
    #pragma unroll
    for (int o = 16; o; o >>= 1) m = fmaxf(m, __shfl_xor_sync(0xffffffffu, m, o));
    if (lane == 0) red[warp] = m;
    __syncthreads();
    if (warp == 0) {
        float v = (lane < 8) ? red[lane] : __int_as_float(0xff800000);
        #pragma unroll
        for (int o = 4; o; o >>= 1) v = fmaxf(v, __shfl_xor_sync(0xffffffffu, v, o));
        if (lane == 0) bval = v;
    }
    __syncthreads();
    float mm = bval;

    float sum = 0.f;
    float* wbuf = w_out + b * S_;
    for (int s = tid; s < S_; s += 256) {
        float e = expf(sc[s] - mm);
        wbuf[s] = e;
        sum += e;
    }
    #pragma unroll
    for (int o = 16; o; o >>= 1) sum += __shfl_xor_sync(0xffffffffu, sum, o);
    if (lane == 0) red[warp] = sum;
    __syncthreads();
    if (warp == 0) {
        float v = (lane < 8) ? red[lane] : 0.f;
        #pragma unroll
        for (int o = 4; o; o >>= 1) v += __shfl_xor_sync(0xffffffffu, v, o);
        if (lane == 0) bval = v;
    }
    __syncthreads();
    float inv = 1.0f / bval;
    for (int s = tid; s < S_; s += 256) wbuf[s] *= inv;
}

// ---------------- kernel 4: context = attn @ values (split-S, skip w==0) -------
__global__ void context_part_kernel(const float* __restrict__ values,
                                    const float* __restrict__ w) {
    int b = blockIdx.x >> 5;
    int p = blockIdx.x & 31;
    int tid = threadIdx.x;
    int s0 = p * (S_ / CSPLIT);
    const float4* vp = (const float4*)(values + ((size_t)b * S_ + s0) * V_) + tid;
    const float* wb = w + b * S_ + s0;
    float4 acc = make_float4(0.f, 0.f, 0.f, 0.f);
    for (int s = 0; s < S_ / CSPLIT; s++) {
        float ws = __ldg(wb + s);
        if (ws != 0.f) {
            float4 v = __ldg(vp + (size_t)s * (V_ / 4));
            acc.x += ws * v.x; acc.y += ws * v.y;
            acc.z += ws * v.z; acc.w += ws * v.w;
        }
    }
    ((float4*)g_ctx_part)[((size_t)p * B_ + b) * (V_ / 4) + tid] = acc;
}

__global__ void context_reduce_kernel(float* __restrict__ ctx) {
    int b = blockIdx.x, tid = threadIdx.x;
    for (int i = tid; i < V_; i += 256) {
        float s = 0.f;
        #pragma unroll
        for (int p = 0; p < CSPLIT; p++) s += g_ctx_part[((size_t)p * B_ + b) * V_ + i];
        ctx[b * V_ + i] = s;
    }
}

// ---------------- launch ----------------
extern "C" void kernel_launch(void* const* d_in, const int* in_sizes, int n_in,
                              void* d_out, int out_size) {
    const float* query  = (const float*)d_in[0];
    const float* keys   = (const float*)d_in[1];
    const float* values = (const float*)d_in[2];
    const int*   mask   = (const int*)d_in[3];
    const float* Wq_w   = (const float*)d_in[4];
    const float* Wq_b   = (const float*)d_in[5];
    const float* Wk_w   = (const float*)d_in[6];
    const float* Wk_b   = (const float*)d_in[7];
    const float* v_w    = (const float*)d_in[8];
    (void)in_sizes; (void)n_in; (void)out_size;

    float* out     = (float*)d_out;
    float* out_ctx = out;             // context: [32,1024]
    float* out_w   = out + B_ * V_;   // attention_weights: [32,4096]

    cudaFuncSetAttribute(scores_kernel,
                         cudaFuncAttributeMaxDynamicSharedMemorySize, DSMEM_BYTES);

    init_kernel<<<(B_ * S_) / 1024, 1024>>>();
    compact_kernel<<<B_, 256>>>(mask);
    gather_keys_kernel<<<B_ * TILES_PER_B, 256>>>(keys);
    convert_wk_kernel<<<(H_ * K_) / (256 * 8), 256>>>(Wk_w);
    qproj_kernel<<<dim3(B_, H_ / 128), 256>>>(query, Wq_w, Wq_b, Wk_b);
    scores_kernel<<<B_ * TILES_PER_B, 512, DSMEM_BYTES>>>(v_w);
    softmax_kernel<<<B_, 256>>>(out_w);
    context_part_kernel<<<B_ * CSPLIT, 256>>>(values, out_w);
    context_reduce_kernel<<<B_, 256>>>(out_ctx);
}